// round 16
// baseline (speedup 1.0000x reference)
#include <cuda_runtime.h>
#include <cuda_fp16.h>
#include <math.h>
#include <stdint.h>

// ---------------------------------------------------------------------------
// TextGRUClassifier: 2-layer bidir GRU (B=256,T=512,E=128,H=160) + FC head
// R16 = R15 with GEMM pipeline deepened to 3 stages (dynamic smem, always-
// commit + wait_group 2 -> DRAM latency covered by two compute phases) and
// the grid transposed (n fastest) so A m-tiles get L2 reuse across n-blocks.
// Scans / convert / head unchanged from R15.
// ---------------------------------------------------------------------------

#define Tt 512
#define Bb 256
#define Hh 160
#define G3 480
#define Mrows (Tt*Bb)     // 131072
#define VV 110000

// ---- scratch ----
static __device__ __half g_gi0[(size_t)2 * Mrows * G3];  // [dir][t][n=480][b=256]
static __device__ __half g_gi1[(size_t)2 * Mrows * G3];
static __device__ __half g_y0h[(size_t)Mrows * 320];     // [t][b][320] permuted-k fp16
static __device__ __half g_embh[(size_t)VV * 128];       // permuted-k fp16
static __device__ __half g_w0h[2 * G3 * 128];            // [dir][n][128] permuted-k
static __device__ __half g_w1h[2 * G3 * 320];            // [dir][n][320] permuted-k
static __device__ float  g_hfin[2 * Bb * Hh];            // [dir][b][g]

// ---- helpers ----
__device__ __forceinline__ float tanh_ap(float x) {
    float r;
    asm("tanh.approx.f32 %0, %1;" : "=f"(r) : "f"(x));
    return r;
}
__device__ __forceinline__ uint32_t f2tf32(float x) {
    uint32_t r;
    asm("cvt.rna.tf32.f32 %0, %1;" : "=r"(r) : "f"(x));
    return r;
}
__device__ __forceinline__ void mma_tf32(float* d, const uint32_t* a, const uint32_t* b) {
    asm volatile(
        "mma.sync.aligned.m16n8k8.row.col.f32.tf32.tf32.f32 "
        "{%0,%1,%2,%3}, {%4,%5,%6,%7}, {%8,%9}, {%0,%1,%2,%3};"
        : "+f"(d[0]), "+f"(d[1]), "+f"(d[2]), "+f"(d[3])
        : "r"(a[0]), "r"(a[1]), "r"(a[2]), "r"(a[3]), "r"(b[0]), "r"(b[1]));
}
__device__ __forceinline__ void mma_f16(float* d, const uint32_t* a, uint32_t b0, uint32_t b1) {
    asm volatile(
        "mma.sync.aligned.m16n8k16.row.col.f32.f16.f16.f32 "
        "{%0,%1,%2,%3}, {%4,%5,%6,%7}, {%8,%9}, {%0,%1,%2,%3};"
        : "+f"(d[0]), "+f"(d[1]), "+f"(d[2]), "+f"(d[3])
        : "r"(a[0]), "r"(a[1]), "r"(a[2]), "r"(a[3]), "r"(b0), "r"(b1));
}
__device__ __forceinline__ uint32_t smem_u32(const void* p) {
    uint32_t a;
    asm("{ .reg .u64 t; cvta.to.shared.u64 t, %1; cvt.u32.u64 %0, t; }" : "=r"(a) : "l"(p));
    return a;
}
__device__ __forceinline__ uint32_t mapa_peer(uint32_t addr, uint32_t rank) {
    uint32_t r;
    asm("mapa.shared::cluster.u32 %0, %1, %2;" : "=r"(r) : "r"(addr), "r"(rank));
    return r;
}
__device__ __forceinline__ void st_cluster_u32(uint32_t addr, uint32_t v) {
    asm volatile("st.shared::cluster.u32 [%0], %1;" :: "r"(addr), "r"(v) : "memory");
}
__device__ __forceinline__ void cp_async16(uint32_t dst, const void* src) {
    asm volatile("cp.async.ca.shared.global [%0], [%1], 16;" :: "r"(dst), "l"(src) : "memory");
}
__device__ __forceinline__ void cp_commit() {
    asm volatile("cp.async.commit_group;" ::: "memory");
}
__device__ __forceinline__ void cp_wait1() {
    asm volatile("cp.async.wait_group 1;" ::: "memory");
}
__device__ __forceinline__ void cp_wait2() {
    asm volatile("cp.async.wait_group 2;" ::: "memory");
}
__device__ __forceinline__ void mbar_init(uint32_t addr, uint32_t count) {
    asm volatile("mbarrier.init.shared.b64 [%0], %1;" :: "r"(addr), "r"(count) : "memory");
}
__device__ __forceinline__ void mbar_arrive_peer(uint32_t remote_addr) {
    asm volatile("mbarrier.arrive.release.cluster.shared::cluster.b64 _, [%0];"
                 :: "r"(remote_addr) : "memory");
}
__device__ __forceinline__ void mbar_wait_parity(uint32_t addr, uint32_t parity) {
    uint32_t done;
    asm volatile(
        "{\n\t.reg .pred p;\n\t"
        "mbarrier.try_wait.parity.acquire.cluster.shared::cta.b64 p, [%1], %2;\n\t"
        "selp.b32 %0, 1, 0, p;\n\t}"
        : "=r"(done) : "r"(addr), "r"(parity) : "memory");
    if (!done) {
        asm volatile(
            "{\n\t.reg .pred P1;\n\t"
            "WAIT_LOOP_%=:\n\t"
            "mbarrier.try_wait.parity.acquire.cluster.shared::cta.b64 P1, [%0], %1, 0x989680;\n\t"
            "@P1 bra.uni WAIT_DONE_%=;\n\t"
            "bra.uni WAIT_LOOP_%=;\n\t"
            "WAIT_DONE_%=:\n\t}"
            :: "r"(addr), "r"(parity) : "memory");
    }
}
#define CLUSTER_SYNC() do { \
    asm volatile("barrier.cluster.arrive.aligned;" ::: "memory"); \
    asm volatile("barrier.cluster.wait.aligned;" ::: "memory"); \
} while (0)

// runtime k-permutation within a 16-group (order [k0k1 k8k9 | k2k3 k10k11 | ...])
__device__ __forceinline__ int hslot_rt(int j) {
    return (j < 8) ? (((j >> 1) << 2) | (j & 1)) : ((((j - 8) >> 1) << 2) + 2 + (j & 1));
}

// ---------------------------------------------------------------------------
// K0: convert fp32 row-major -> fp16 with permuted k 16-groups.
// ---------------------------------------------------------------------------
__global__ void convert_permute_kernel(const float* __restrict__ src,
                                       __half* __restrict__ dst,
                                       int rows, int K) {
    long long idx = (long long)blockIdx.x * blockDim.x + threadIdx.x;
    long long total = (long long)rows * (K >> 1);
    if (idx >= total) return;
    int Kh = K >> 1;
    int row = (int)(idx / Kh);
    int p = (int)(idx - (long long)row * Kh);
    int kk = p << 1;
    int group = kk >> 4;
    int jp = (kk >> 1) & 7;
    int slot = (jp < 4) ? jp * 4 : (jp - 4) * 4 + 2;
    float2 v = *(const float2*)(src + (size_t)row * K + kk);
    *(__half2*)(dst + (size_t)row * K + group * 16 + slot) = __floats2half2_rn(v.x, v.y);
}

// ---------------------------------------------------------------------------
// K1/K3: gates GEMM, pure-cp.async f16 pipeline, 3 stages (dynamic smem).
//   grid: (n-blocks=5, m-blocks=1024, dir=2)  -- n fastest for A L2 reuse.
//   out (half): [dir][t][n=480][b=256].
// ---------------------------------------------------------------------------
#define HRS 48                       // halves per smem tile row
#define STAGE_H (128 * HRS + 96 * HRS)   // halves per stage: 10752
#define GSMEM_BYTES (3 * STAGE_H * 2)    // 64512

template <int KDIM, bool GATHER>
__global__ __launch_bounds__(256, 2)
void gates_mma_kernel(const __half* __restrict__ A, const int* __restrict__ xids,
                      const __half* __restrict__ Wall,
                      const float* __restrict__ bf, const float* __restrict__ bb,
                      __half* __restrict__ out) {
    const int m0 = blockIdx.y * 128;
    const int n0 = blockIdx.x * 96;
    const int dir = blockIdx.z;
    const __half* W = Wall + (size_t)dir * G3 * KDIM;
    const float* bias = dir ? bb : bf;
    __half* outp = out + (size_t)dir * Mrows * G3;

    extern __shared__ __align__(16) __half dsm[];   // 3 stages: [A 6144 | B 4608]
    __shared__ int rid[128];

    const int tid = threadIdx.x;
    if (GATHER) {
        if (tid < 128) {
            int m = m0 + tid;
            rid[tid] = xids[(m & 255) * Tt + (m >> 8)];
        }
        __syncthreads();
    }

    const int lane = tid & 31, wid = tid >> 5;
    const int grp = lane >> 2, tq = lane & 3;
    const int m_off = (wid >> 1) * 32;
    const int n_off = (wid & 1) * 48;

    float acc[2][6][4];
#pragma unroll
    for (int i = 0; i < 2; i++)
#pragma unroll
        for (int j = 0; j < 6; j++)
#pragma unroll
            for (int c = 0; c < 4; c++) acc[i][j][c] = 0.f;

    // ---- cp.async chunk assignment: 16B chunks, 4 per 32-half tile row ----
    const int off8 = (tid & 3) * 8;
    const int r0 = tid >> 2;               // 0..63
    const __half* aptr0;
    const __half* aptr1;
    if (GATHER) {
        aptr0 = A + (size_t)rid[r0] * KDIM;
        aptr1 = A + (size_t)rid[r0 + 64] * KDIM;
    } else {
        aptr0 = A + (size_t)(m0 + r0) * KDIM;
        aptr1 = A + (size_t)(m0 + r0 + 64) * KDIM;
    }
    const __half* bptr0 = W + (size_t)(n0 + r0) * KDIM;
    const __half* bptr1 = (tid < 128) ? W + (size_t)(n0 + r0 + 64) * KDIM : W;

    uint32_t adst[3], adst2[3], bdst[3], bdst2[3];
#pragma unroll
    for (int s = 0; s < 3; s++) {
        __half* As = dsm + s * STAGE_H;
        __half* Bs = As + 128 * HRS;
        adst[s]  = smem_u32(As + r0 * HRS + off8);
        adst2[s] = smem_u32(As + (r0 + 64) * HRS + off8);
        bdst[s]  = smem_u32(Bs + r0 * HRS + off8);
        bdst2[s] = smem_u32(Bs + (r0 + 64) * HRS + off8);
    }

    const int KT = KDIM / 32;

    // prologue: stage tiles 0 and 1 as separate commit groups
#pragma unroll
    for (int p = 0; p < 2; p++) {
        const int ko = p * 32 + off8;
        cp_async16(adst[p],  aptr0 + ko);
        cp_async16(adst2[p], aptr1 + ko);
        cp_async16(bdst[p],  bptr0 + ko);
        if (tid < 128) cp_async16(bdst2[p], bptr1 + ko);
        cp_commit();
    }

    for (int kt = 0; kt < KT; kt++) {
        const int buf = kt % 3;
        // issue tile kt+2 (into the buffer computed at kt-1; safe past barB)
        if (kt + 2 < KT) {
            const int nb = (kt + 2) % 3;
            const int ko = (kt + 2) * 32 + off8;
            cp_async16(adst[nb],  aptr0 + ko);
            cp_async16(adst2[nb], aptr1 + ko);
            cp_async16(bdst[nb],  bptr0 + ko);
            if (tid < 128) cp_async16(bdst2[nb], bptr1 + ko);
        }
        cp_commit();          // always commit (possibly empty) to keep counts
        cp_wait2();           // tile kt's group complete (kt+1, kt+2 in flight)
        __syncthreads();

        const __half* As = dsm + buf * STAGE_H;
        const __half* Bs = As + 128 * HRS;
#pragma unroll
        for (int g = 0; g < 2; g++) {
            const int goff = g * 16 + tq * 4;
            uint32_t af[2][4];
#pragma unroll
            for (int i = 0; i < 2; i++) {
                int rm = m_off + i * 16;
                uint2 v0 = *(const uint2*)&As[(rm + grp) * HRS + goff];
                uint2 v1 = *(const uint2*)&As[(rm + 8 + grp) * HRS + goff];
                af[i][0] = v0.x; af[i][1] = v1.x; af[i][2] = v0.y; af[i][3] = v1.y;
            }
#pragma unroll
            for (int j = 0; j < 6; j++) {
                uint2 bv = *(const uint2*)&Bs[(n_off + j * 8 + grp) * HRS + goff];
                mma_f16(acc[0][j], af[0], bv.x, bv.y);
                mma_f16(acc[1][j], af[1], bv.x, bv.y);
            }
        }
        __syncthreads();      // buf free before cp.async targets it next iter
    }

    // epilogue -> half out[t][n][256]
    {
        const int t_t = m0 >> 8;
        const int bb2 = m0 & 255;
        __half* ob = outp + (size_t)t_t * G3 * 256 + bb2;
#pragma unroll
        for (int j = 0; j < 6; j++) {
            int col = n0 + n_off + j * 8 + 2 * tq;
            float b0v = bias[col], b1v = bias[col + 1];
#pragma unroll
            for (int i = 0; i < 2; i++) {
                int ml = m_off + i * 16 + grp;
                ob[(size_t)col * 256 + ml]           = __float2half(acc[i][j][0] + b0v);
                ob[(size_t)(col + 1) * 256 + ml]     = __float2half(acc[i][j][1] + b1v);
                ob[(size_t)col * 256 + ml + 8]       = __float2half(acc[i][j][2] + b0v);
                ob[(size_t)(col + 1) * 256 + ml + 8] = __float2half(acc[i][j][3] + b1v);
            }
        }
    }
}

// ---------------------------------------------------------------------------
// K2/K4: GRU scan on tensor cores, 2-CTA cluster (R15 verbatim).
// ---------------------------------------------------------------------------
#define HST 168                  // h row stride (floats); 168 % 32 == 8
#define HBUFN (8 * HST)
#define GROWS 240                // gi rows staged per step (3 gates x 80 units)

__global__ __launch_bounds__(512) __cluster_dims__(2, 1, 1)
void scan_mma_kernel(const __half* __restrict__ gi,
                     const float* __restrict__ whhF, const float* __restrict__ whhB,
                     const float* __restrict__ bhf, const float* __restrict__ bhb,
                     void* __restrict__ yout, int layer) {
    __shared__ __align__(16) float hbuf[2][HBUFN];   // [buf][b][perm(k)] (tf32 bits)
    __shared__ float gh[240 * 8];                    // [lr][b]
    __shared__ __align__(16) __half gis[2][GROWS * 8];
    __shared__ __align__(8) unsigned long long mbar[2];

    const int dir = blockIdx.y;
    const int rank = blockIdx.x & 1;
    const int b0 = (blockIdx.x >> 1) * 8;
    const int tid = threadIdx.x;
    const int wid = tid >> 5, lane = tid & 31;
    const int grp = lane >> 2, tq = lane & 3;

    const uint32_t mbar0 = smem_u32(&mbar[0]);
    const uint32_t mbar1 = smem_u32(&mbar[1]);
    const uint32_t pbar0 = mapa_peer(mbar0, rank ^ 1);
    const uint32_t pbar1 = mapa_peer(mbar1, rank ^ 1);
    if (tid == 0) {
        mbar_init(mbar0, 1);
        mbar_init(mbar1, 1);
    }

    // ---- preload Whh A-fragments: [0..39] own-rank k half, [40..79] peer half ----
    uint32_t wreg[80];
    const bool is_mma = (wid < 15);
    const int ktL = rank * 10;
    const int ktR = (rank ^ 1) * 10;
    if (is_mma) {
        const int gate = wid / 5, mseg = wid % 5;
        const int gr0 = gate * Hh + rank * 80 + mseg * 16 + grp;
        const float* W = dir ? whhB : whhF;
#pragma unroll
        for (int j = 0; j < 10; j++) {
            int kt = ktL + j;
            wreg[j * 4 + 0] = f2tf32(W[(size_t)gr0 * Hh + kt * 8 + tq]);
            wreg[j * 4 + 1] = f2tf32(W[(size_t)(gr0 + 8) * Hh + kt * 8 + tq]);
            wreg[j * 4 + 2] = f2tf32(W[(size_t)gr0 * Hh + kt * 8 + tq + 4]);
            wreg[j * 4 + 3] = f2tf32(W[(size_t)(gr0 + 8) * Hh + kt * 8 + tq + 4]);
        }
#pragma unroll
        for (int j = 0; j < 10; j++) {
            int kt = ktR + j;
            wreg[40 + j * 4 + 0] = f2tf32(W[(size_t)gr0 * Hh + kt * 8 + tq]);
            wreg[40 + j * 4 + 1] = f2tf32(W[(size_t)(gr0 + 8) * Hh + kt * 8 + tq]);
            wreg[40 + j * 4 + 2] = f2tf32(W[(size_t)gr0 * Hh + kt * 8 + tq + 4]);
            wreg[40 + j * 4 + 3] = f2tf32(W[(size_t)(gr0 + 8) * Hh + kt * 8 + tq + 4]);
        }
    }

    // ---- combine-item setup ----
    const int uA = tid >> 3, bA = tid & 7;
    const int gA = rank * 80 + uA;
    const int pgA = (gA & ~7) | (((gA & 3) << 1) | ((gA >> 2) & 1));
    const float* bh = dir ? bhb : bhf;
    const float bhrA = bh[gA], bhzA = bh[Hh + gA], bhnA = bh[2 * Hh + gA];
    uint32_t prA[2];
    prA[0] = mapa_peer(smem_u32(&hbuf[0][bA * HST + pgA]), rank ^ 1);
    prA[1] = mapa_peer(smem_u32(&hbuf[1][bA * HST + pgA]), rank ^ 1);

    const bool hasB = (tid < 128);
    const int uB = 64 + (tid >> 3), gB = rank * 80 + uB;
    const int pgB = (gB & ~7) | (((gB & 3) << 1) | ((gB >> 2) & 1));
    float bhrB = 0.f, bhzB = 0.f, bhnB = 0.f;
    uint32_t prB[2] = {0u, 0u};
    if (hasB) {
        bhrB = bh[gB]; bhzB = bh[Hh + gB]; bhnB = bh[2 * Hh + gB];
        prB[0] = mapa_peer(smem_u32(&hbuf[0][bA * HST + pgB]), rank ^ 1);
        prB[1] = mapa_peer(smem_u32(&hbuf[1][bA * HST + pgB]), rank ^ 1);
    }

    // ---- y0 permuted-fp16 column indices (GEMM1 fragment layout) ----
    const int cA = dir * Hh + gA;
    const int ycA = (cA & ~15) | hslot_rt(cA & 15);
    const int cB = dir * Hh + gB;
    const int ycB = (cB & ~15) | hslot_rt(cB & 15);

    // ---- gi staging: thread r<240 owns one (gate,unit) row of 8 halves ----
    const __half* gib = gi + (size_t)dir * Mrows * G3;
    const bool is_ld = (tid < GROWS);
    const int rgate = tid / 80;
    const int runit = tid - rgate * 80;
    const int rn = rgate * 160 + rank * 80 + runit;
    const __half* srcRow = gib + (size_t)rn * 256 + b0;
    const uint32_t gis_base = smem_u32(&gis[0][0]);
    const uint32_t dstRow = gis_base + (uint32_t)tid * 16;

    for (int i = tid; i < 2 * HBUFN; i += 512) (&hbuf[0][0])[i] = 0.f;

    // prologue: stage gi for s=0 into slot 0
    {
        const int t0 = dir ? (Tt - 1) : 0;
        if (is_ld) cp_async16(dstRow, srcRow + (size_t)t0 * G3 * 256);
        cp_commit();
    }

    __syncthreads();
    CLUSTER_SYNC();

    float hA = 0.f, hB = 0.f;
    int cur = 0;

    for (int s = 0; s < Tt; s++) {
        if (s + 1 < Tt) {
            const int tn = dir ? (Tt - 2 - s) : (s + 1);
            if (is_ld) cp_async16(dstRow + (cur ^ 1) * (GROWS * 16),
                                  srcRow + (size_t)tn * G3 * 256);
        }
        cp_commit();

        if (is_mma) {
            float accA[4] = {0.f, 0.f, 0.f, 0.f};
            float accB4[4] = {0.f, 0.f, 0.f, 0.f};
            const float* hc = hbuf[cur];
            const int hbase = grp * HST;

            // phase L: own-half k (no peer dependency)
#pragma unroll
            for (int j = 0; j < 10; j += 2) {
                float2 v0 = *(const float2*)&hc[hbase + (ktL + j) * 8 + tq * 2];
                mma_tf32(accA, &wreg[j * 4], (const uint32_t*)&v0);
                float2 v1 = *(const float2*)&hc[hbase + (ktL + j + 1) * 8 + tq * 2];
                mma_tf32(accB4, &wreg[(j + 1) * 4], (const uint32_t*)&v1);
            }

            if (s > 0) {
                mbar_wait_parity((s & 1) ? mbar1 : mbar0, ((s - 1) >> 1) & 1);
            }

            // phase R: peer-half k
#pragma unroll
            for (int j = 0; j < 10; j += 2) {
                float2 v0 = *(const float2*)&hc[hbase + (ktR + j) * 8 + tq * 2];
                mma_tf32(accA, &wreg[40 + j * 4], (const uint32_t*)&v0);
                float2 v1 = *(const float2*)&hc[hbase + (ktR + j + 1) * 8 + tq * 2];
                mma_tf32(accB4, &wreg[40 + (j + 1) * 4], (const uint32_t*)&v1);
            }

            const int lr = wid * 16;
            *(float2*)&gh[(lr + grp) * 8 + 2 * tq] =
                make_float2(accA[0] + accB4[0], accA[1] + accB4[1]);
            *(float2*)&gh[(lr + 8 + grp) * 8 + 2 * tq] =
                make_float2(accA[2] + accB4[2], accA[3] + accB4[3]);
        }
        cp_wait1();
        __syncthreads();

        const int t = dir ? (Tt - 1 - s) : s;
        const int nxt = cur ^ 1;
        const __half* gs = &gis[cur][0];
        {
            float gir = __half2float(gs[(0 * 80 + uA) * 8 + bA]);
            float giz = __half2float(gs[(1 * 80 + uA) * 8 + bA]);
            float gin = __half2float(gs[(2 * 80 + uA) * 8 + bA]);
            float r = fmaf(tanh_ap(0.5f * (gir + gh[uA * 8 + bA] + bhrA)), 0.5f, 0.5f);
            float z = fmaf(tanh_ap(0.5f * (giz + gh[(80 + uA) * 8 + bA] + bhzA)), 0.5f, 0.5f);
            float n = tanh_ap(gin + r * (gh[(160 + uA) * 8 + bA] + bhnA));
            hA = fmaf(z, hA - n, n);
            uint32_t htf = f2tf32(hA);
            *(uint32_t*)&hbuf[nxt][bA * HST + pgA] = htf;
            st_cluster_u32(prA[nxt], htf);
            if (layer == 0)
                ((__half*)yout)[((size_t)t * 256 + b0 + bA) * 320 + ycA] = __float2half(hA);
        }
        if (hasB) {
            float gir = __half2float(gs[(0 * 80 + uB) * 8 + bA]);
            float giz = __half2float(gs[(1 * 80 + uB) * 8 + bA]);
            float gin = __half2float(gs[(2 * 80 + uB) * 8 + bA]);
            float r = fmaf(tanh_ap(0.5f * (gir + gh[uB * 8 + bA] + bhrB)), 0.5f, 0.5f);
            float z = fmaf(tanh_ap(0.5f * (giz + gh[(80 + uB) * 8 + bA] + bhzB)), 0.5f, 0.5f);
            float n = tanh_ap(gin + r * (gh[(160 + uB) * 8 + bA] + bhnB));
            hB = fmaf(z, hB - n, n);
            uint32_t htf = f2tf32(hB);
            *(uint32_t*)&hbuf[nxt][bA * HST + pgB] = htf;
            st_cluster_u32(prB[nxt], htf);
            if (layer == 0)
                ((__half*)yout)[((size_t)t * 256 + b0 + bA) * 320 + ycB] = __float2half(hB);
        }
        __syncthreads();   // all peer stores issued before the release below
        if (tid == 0) {
            mbar_arrive_peer((nxt & 1) ? pbar1 : pbar0);
        }
        cur = nxt;
    }

    if (layer == 1) {
        float* hf = (float*)yout;
        hf[((size_t)(dir * Bb) + b0 + bA) * Hh + gA] = hA;
        if (hasB) hf[((size_t)(dir * Bb) + b0 + bA) * Hh + gB] = hB;
    }
    CLUSTER_SYNC();   // no CTA exits while peer stores into its smem may be in flight
}

// ---------------------------------------------------------------------------
// K5: head
// ---------------------------------------------------------------------------
__global__ __launch_bounds__(128)
void head_kernel(const float* __restrict__ hfin,
                 const float* __restrict__ fc1w, const float* __restrict__ fc1b,
                 const float* __restrict__ fc2w, const float* __restrict__ fc2b,
                 float* __restrict__ out) {
    const int b = blockIdx.x;
    const int j = threadIdx.x;
    __shared__ float hv[320];
    __shared__ float red[4];

    for (int k = j; k < Hh; k += 128) {
        hv[k]      = hfin[(size_t)b * Hh + k];
        hv[Hh + k] = hfin[(size_t)Bb * Hh + (size_t)b * Hh + k];
    }
    __syncthreads();

    float acc = fc1b[j];
    const float* wr = fc1w + (size_t)j * 320;
#pragma unroll 8
    for (int k = 0; k < 320; k++) acc += wr[k] * hv[k];
    float v = fmaxf(acc, 0.f) * fc2w[j];

#pragma unroll
    for (int o = 16; o > 0; o >>= 1) v += __shfl_down_sync(0xffffffffu, v, o);
    if ((j & 31) == 0) red[j >> 5] = v;
    __syncthreads();
    if (j == 0) out[b] = red[0] + red[1] + red[2] + red[3] + fc2b[0];
}

// ---------------------------------------------------------------------------
// kernel_launch — sequential pipeline (graph-capturable, profiler-safe)
// ---------------------------------------------------------------------------
extern "C" void kernel_launch(void* const* d_in, const int* in_sizes, int n_in,
                              void* d_out, int out_size) {
    const int*   x        = (const int*)  d_in[0];
    const float* emb      = (const float*)d_in[1];
    const float* Wih_l0f  = (const float*)d_in[2];
    const float* Whh_l0f  = (const float*)d_in[3];
    const float* bih_l0f  = (const float*)d_in[4];
    const float* bhh_l0f  = (const float*)d_in[5];
    const float* Wih_l0b  = (const float*)d_in[6];
    const float* Whh_l0b  = (const float*)d_in[7];
    const float* bih_l0b  = (const float*)d_in[8];
    const float* bhh_l0b  = (const float*)d_in[9];
    const float* Wih_l1f  = (const float*)d_in[10];
    const float* Whh_l1f  = (const float*)d_in[11];
    const float* bih_l1f  = (const float*)d_in[12];
    const float* bhh_l1f  = (const float*)d_in[13];
    const float* Wih_l1b  = (const float*)d_in[14];
    const float* Whh_l1b  = (const float*)d_in[15];
    const float* bih_l1b  = (const float*)d_in[16];
    const float* bhh_l1b  = (const float*)d_in[17];
    const float* fc1_w    = (const float*)d_in[18];
    const float* fc1_b    = (const float*)d_in[19];
    const float* fc2_w    = (const float*)d_in[20];
    const float* fc2_b    = (const float*)d_in[21];
    float* out = (float*)d_out;

    __half *gi0, *gi1, *y0h, *embh, *w0h, *w1h;
    float *hfin;
    cudaGetSymbolAddress((void**)&gi0,  g_gi0);
    cudaGetSymbolAddress((void**)&gi1,  g_gi1);
    cudaGetSymbolAddress((void**)&y0h,  g_y0h);
    cudaGetSymbolAddress((void**)&embh, g_embh);
    cudaGetSymbolAddress((void**)&w0h,  g_w0h);
    cudaGetSymbolAddress((void**)&w1h,  g_w1h);
    cudaGetSymbolAddress((void**)&hfin, g_hfin);

    static int attr_set = 0;
    if (!attr_set) {
        cudaFuncSetAttribute(gates_mma_kernel<128, true>,
                             cudaFuncAttributeMaxDynamicSharedMemorySize, GSMEM_BYTES);
        cudaFuncSetAttribute(gates_mma_kernel<320, false>,
                             cudaFuncAttributeMaxDynamicSharedMemorySize, GSMEM_BYTES);
        attr_set = 1;
    }

    // K0: convert operands to permuted fp16
    {
        long long n = (long long)VV * 64;
        convert_permute_kernel<<<(unsigned)((n + 255) / 256), 256>>>(emb, embh, VV, 128);
        convert_permute_kernel<<<(G3 * 64 + 255) / 256, 256>>>(Wih_l0f, w0h, G3, 128);
        convert_permute_kernel<<<(G3 * 64 + 255) / 256, 256>>>(Wih_l0b, w0h + G3 * 128, G3, 128);
        convert_permute_kernel<<<(G3 * 160 + 255) / 256, 256>>>(Wih_l1f, w1h, G3, 320);
        convert_permute_kernel<<<(G3 * 160 + 255) / 256, 256>>>(Wih_l1b, w1h + G3 * 320, G3, 320);
    }

    {
        dim3 grid(G3 / 96, Mrows / 128, 2);   // n fastest -> A-tile L2 reuse
        gates_mma_kernel<128, true><<<grid, 256, GSMEM_BYTES>>>(embh, x, w0h,
                                                                bih_l0f, bih_l0b, gi0);
    }

    scan_mma_kernel<<<dim3(64, 2), 512>>>(gi0, Whh_l0f, Whh_l0b,
                                          bhh_l0f, bhh_l0b, y0h, 0);

    {
        dim3 grid(G3 / 96, Mrows / 128, 2);
        gates_mma_kernel<320, false><<<grid, 256, GSMEM_BYTES>>>(y0h, nullptr, w1h,
                                                                 bih_l1f, bih_l1b, gi1);
    }

    scan_mma_kernel<<<dim3(64, 2), 512>>>(gi1, Whh_l1f, Whh_l1b,
                                          bhh_l1f, bhh_l1b, hfin, 1);

    head_kernel<<<Bb, 128>>>(hfin, fc1_w, fc1_b, fc2_w, fc2_b, out);
}

// round 17
// speedup vs baseline: 1.0372x; 1.0372x over previous
#include <cuda_runtime.h>
#include <cuda_fp16.h>
#include <math.h>
#include <stdint.h>

// ---------------------------------------------------------------------------
// TextGRUClassifier: 2-layer bidir GRU (B=256,T=512,E=128,H=160) + FC head
// R17 = R15 GEMMs (2-stage cp.async f16, measured-best) + scan h-dot moved to
// f16 m16n8k16 mma: half the mma count/fragment loads, 40 weight regs, fp16
// hbuf (hslot-permuted, HSTH=208 conflict-free), u16 peer pushes.
// ---------------------------------------------------------------------------

#define Tt 512
#define Bb 256
#define Hh 160
#define G3 480
#define Mrows (Tt*Bb)     // 131072
#define VV 110000

// ---- scratch ----
static __device__ __half g_gi0[(size_t)2 * Mrows * G3];  // [dir][t][n=480][b=256]
static __device__ __half g_gi1[(size_t)2 * Mrows * G3];
static __device__ __half g_y0h[(size_t)Mrows * 320];     // [t][b][320] permuted-k fp16
static __device__ __half g_embh[(size_t)VV * 128];       // permuted-k fp16
static __device__ __half g_w0h[2 * G3 * 128];            // [dir][n][128] permuted-k
static __device__ __half g_w1h[2 * G3 * 320];            // [dir][n][320] permuted-k
static __device__ float  g_hfin[2 * Bb * Hh];            // [dir][b][g]

// ---- helpers ----
__device__ __forceinline__ float tanh_ap(float x) {
    float r;
    asm("tanh.approx.f32 %0, %1;" : "=f"(r) : "f"(x));
    return r;
}
__device__ __forceinline__ uint32_t packh2(float x, float y) {
    __half2 h = __floats2half2_rn(x, y);
    return *(uint32_t*)&h;
}
__device__ __forceinline__ void mma_f16(float* d, const uint32_t* a, uint32_t b0, uint32_t b1) {
    asm volatile(
        "mma.sync.aligned.m16n8k16.row.col.f32.f16.f16.f32 "
        "{%0,%1,%2,%3}, {%4,%5,%6,%7}, {%8,%9}, {%0,%1,%2,%3};"
        : "+f"(d[0]), "+f"(d[1]), "+f"(d[2]), "+f"(d[3])
        : "r"(a[0]), "r"(a[1]), "r"(a[2]), "r"(a[3]), "r"(b0), "r"(b1));
}
__device__ __forceinline__ uint32_t smem_u32(const void* p) {
    uint32_t a;
    asm("{ .reg .u64 t; cvta.to.shared.u64 t, %1; cvt.u32.u64 %0, t; }" : "=r"(a) : "l"(p));
    return a;
}
__device__ __forceinline__ uint32_t mapa_peer(uint32_t addr, uint32_t rank) {
    uint32_t r;
    asm("mapa.shared::cluster.u32 %0, %1, %2;" : "=r"(r) : "r"(addr), "r"(rank));
    return r;
}
__device__ __forceinline__ void st_cluster_u16(uint32_t addr, unsigned short v) {
    asm volatile("st.shared::cluster.u16 [%0], %1;" :: "r"(addr), "h"(v) : "memory");
}
__device__ __forceinline__ void cp_async16(uint32_t dst, const void* src) {
    asm volatile("cp.async.ca.shared.global [%0], [%1], 16;" :: "r"(dst), "l"(src) : "memory");
}
__device__ __forceinline__ void cp_commit() {
    asm volatile("cp.async.commit_group;" ::: "memory");
}
__device__ __forceinline__ void cp_wait1() {
    asm volatile("cp.async.wait_group 1;" ::: "memory");
}
__device__ __forceinline__ void cp_wait0() {
    asm volatile("cp.async.wait_group 0;" ::: "memory");
}
__device__ __forceinline__ void mbar_init(uint32_t addr, uint32_t count) {
    asm volatile("mbarrier.init.shared.b64 [%0], %1;" :: "r"(addr), "r"(count) : "memory");
}
__device__ __forceinline__ void mbar_arrive_peer(uint32_t remote_addr) {
    asm volatile("mbarrier.arrive.release.cluster.shared::cluster.b64 _, [%0];"
                 :: "r"(remote_addr) : "memory");
}
__device__ __forceinline__ void mbar_wait_parity(uint32_t addr, uint32_t parity) {
    uint32_t done;
    asm volatile(
        "{\n\t.reg .pred p;\n\t"
        "mbarrier.try_wait.parity.acquire.cluster.shared::cta.b64 p, [%1], %2;\n\t"
        "selp.b32 %0, 1, 0, p;\n\t}"
        : "=r"(done) : "r"(addr), "r"(parity) : "memory");
    if (!done) {
        asm volatile(
            "{\n\t.reg .pred P1;\n\t"
            "WAIT_LOOP_%=:\n\t"
            "mbarrier.try_wait.parity.acquire.cluster.shared::cta.b64 P1, [%0], %1, 0x989680;\n\t"
            "@P1 bra.uni WAIT_DONE_%=;\n\t"
            "bra.uni WAIT_LOOP_%=;\n\t"
            "WAIT_DONE_%=:\n\t}"
            :: "r"(addr), "r"(parity) : "memory");
    }
}
#define CLUSTER_SYNC() do { \
    asm volatile("barrier.cluster.arrive.aligned;" ::: "memory"); \
    asm volatile("barrier.cluster.wait.aligned;" ::: "memory"); \
} while (0)

// runtime k-permutation within a 16-group (order [k0k1 k8k9 | k2k3 k10k11 | ...])
__device__ __forceinline__ int hslot_rt(int j) {
    return (j < 8) ? (((j >> 1) << 2) | (j & 1)) : ((((j - 8) >> 1) << 2) + 2 + (j & 1));
}

// ---------------------------------------------------------------------------
// K0: convert fp32 row-major -> fp16 with permuted k 16-groups.
// ---------------------------------------------------------------------------
__global__ void convert_permute_kernel(const float* __restrict__ src,
                                       __half* __restrict__ dst,
                                       int rows, int K) {
    long long idx = (long long)blockIdx.x * blockDim.x + threadIdx.x;
    long long total = (long long)rows * (K >> 1);
    if (idx >= total) return;
    int Kh = K >> 1;
    int row = (int)(idx / Kh);
    int p = (int)(idx - (long long)row * Kh);
    int kk = p << 1;
    int group = kk >> 4;
    int jp = (kk >> 1) & 7;
    int slot = (jp < 4) ? jp * 4 : (jp - 4) * 4 + 2;
    float2 v = *(const float2*)(src + (size_t)row * K + kk);
    *(__half2*)(dst + (size_t)row * K + group * 16 + slot) = __floats2half2_rn(v.x, v.y);
}

// ---------------------------------------------------------------------------
// K1/K3: gates GEMM, pure-cp.async f16 pipeline (R15 verbatim, 2-stage).
// ---------------------------------------------------------------------------
#define HRS 48    // halves per smem tile row

template <int KDIM, bool GATHER>
__global__ __launch_bounds__(256, 2)
void gates_mma_kernel(const __half* __restrict__ A, const int* __restrict__ xids,
                      const __half* __restrict__ Wall,
                      const float* __restrict__ bf, const float* __restrict__ bb,
                      __half* __restrict__ out) {
    const int m0 = blockIdx.x * 128;
    const int n0 = blockIdx.y * 96;
    const int dir = blockIdx.z;
    const __half* W = Wall + (size_t)dir * G3 * KDIM;
    const float* bias = dir ? bb : bf;
    __half* outp = out + (size_t)dir * Mrows * G3;

    __shared__ __align__(16) __half Ash[2][128 * HRS];
    __shared__ __align__(16) __half Bsh[2][96 * HRS];
    __shared__ int rid[128];

    const int tid = threadIdx.x;
    if (GATHER) {
        if (tid < 128) {
            int m = m0 + tid;
            rid[tid] = xids[(m & 255) * Tt + (m >> 8)];
        }
        __syncthreads();
    }

    const int lane = tid & 31, wid = tid >> 5;
    const int grp = lane >> 2, tq = lane & 3;
    const int m_off = (wid >> 1) * 32;
    const int n_off = (wid & 1) * 48;

    float acc[2][6][4];
#pragma unroll
    for (int i = 0; i < 2; i++)
#pragma unroll
        for (int j = 0; j < 6; j++)
#pragma unroll
            for (int c = 0; c < 4; c++) acc[i][j][c] = 0.f;

    const int off8 = (tid & 3) * 8;
    const int r0 = tid >> 2;
    const __half* aptr0;
    const __half* aptr1;
    if (GATHER) {
        aptr0 = A + (size_t)rid[r0] * KDIM;
        aptr1 = A + (size_t)rid[r0 + 64] * KDIM;
    } else {
        aptr0 = A + (size_t)(m0 + r0) * KDIM;
        aptr1 = A + (size_t)(m0 + r0 + 64) * KDIM;
    }
    const __half* bptr0 = W + (size_t)(n0 + r0) * KDIM;
    const __half* bptr1 = (tid < 128) ? W + (size_t)(n0 + r0 + 64) * KDIM : W;

    uint32_t adst[2], adst2[2], bdst[2], bdst2[2];
#pragma unroll
    for (int b = 0; b < 2; b++) {
        adst[b]  = smem_u32(&Ash[b][r0 * HRS + off8]);
        adst2[b] = smem_u32(&Ash[b][(r0 + 64) * HRS + off8]);
        bdst[b]  = smem_u32(&Bsh[b][r0 * HRS + off8]);
        bdst2[b] = smem_u32(&Bsh[b][(r0 + 64) * HRS + off8]);
    }

    const int KT = KDIM / 32;

    {
        cp_async16(adst[0],  aptr0 + off8);
        cp_async16(adst2[0], aptr1 + off8);
        cp_async16(bdst[0],  bptr0 + off8);
        if (tid < 128) cp_async16(bdst2[0], bptr1 + off8);
        cp_commit();
    }

    for (int kt = 0; kt < KT; kt++) {
        const int buf = kt & 1;
        if (kt + 1 < KT) {
            const int ko = (kt + 1) * 32 + off8;
            const int nb = buf ^ 1;
            cp_async16(adst[nb],  aptr0 + ko);
            cp_async16(adst2[nb], aptr1 + ko);
            cp_async16(bdst[nb],  bptr0 + ko);
            if (tid < 128) cp_async16(bdst2[nb], bptr1 + ko);
            cp_commit();
            cp_wait1();
        } else {
            cp_wait0();
        }
        __syncthreads();

#pragma unroll
        for (int g = 0; g < 2; g++) {
            const int goff = g * 16 + tq * 4;
            uint32_t af[2][4];
#pragma unroll
            for (int i = 0; i < 2; i++) {
                int rm = m_off + i * 16;
                uint2 v0 = *(const uint2*)&Ash[buf][(rm + grp) * HRS + goff];
                uint2 v1 = *(const uint2*)&Ash[buf][(rm + 8 + grp) * HRS + goff];
                af[i][0] = v0.x; af[i][1] = v1.x; af[i][2] = v0.y; af[i][3] = v1.y;
            }
#pragma unroll
            for (int j = 0; j < 6; j++) {
                uint2 bv = *(const uint2*)&Bsh[buf][(n_off + j * 8 + grp) * HRS + goff];
                mma_f16(acc[0][j], af[0], bv.x, bv.y);
                mma_f16(acc[1][j], af[1], bv.x, bv.y);
            }
        }
        __syncthreads();
    }

    {
        const int t_t = m0 >> 8;
        const int bb2 = m0 & 255;
        __half* ob = outp + (size_t)t_t * G3 * 256 + bb2;
#pragma unroll
        for (int j = 0; j < 6; j++) {
            int col = n0 + n_off + j * 8 + 2 * tq;
            float b0v = bias[col], b1v = bias[col + 1];
#pragma unroll
            for (int i = 0; i < 2; i++) {
                int ml = m_off + i * 16 + grp;
                ob[(size_t)col * 256 + ml]           = __float2half(acc[i][j][0] + b0v);
                ob[(size_t)(col + 1) * 256 + ml]     = __float2half(acc[i][j][1] + b1v);
                ob[(size_t)col * 256 + ml + 8]       = __float2half(acc[i][j][2] + b0v);
                ob[(size_t)(col + 1) * 256 + ml + 8] = __float2half(acc[i][j][3] + b1v);
            }
        }
    }
}

// ---------------------------------------------------------------------------
// K2/K4: GRU scan, f16 m16n8k16 mma, 2-CTA cluster.
//   CTA rank r owns gate rows for units [r*80,+80) = 15 m16 tiles.
//   Whh in 40 half2 regs/thread: [0..19] own k half (kt=rank*5+j), [20..39] peer.
//   hbuf: fp16 [buf][b=8][HSTH=208] with hslot-permuted k 16-groups; fragment
//   uint2 at [grp*HSTH + kt*16 + tq*4] = B regs (b0,b1). Peer push = u16.
// ---------------------------------------------------------------------------
#define HSTH 208                 // halves per hbuf row; (HSTH/2)%32==8 -> conflict-free
#define HBUFN (8 * HSTH)
#define GROWS 240

__global__ __launch_bounds__(512) __cluster_dims__(2, 1, 1)
void scan_mma_kernel(const __half* __restrict__ gi,
                     const float* __restrict__ whhF, const float* __restrict__ whhB,
                     const float* __restrict__ bhf, const float* __restrict__ bhb,
                     void* __restrict__ yout, int layer) {
    __shared__ __align__(16) __half hbuf[2][HBUFN];  // fp16 h, permuted k
    __shared__ float gh[240 * 8];                    // [lr][b]
    __shared__ __align__(16) __half gis[2][GROWS * 8];
    __shared__ __align__(8) unsigned long long mbar[2];

    const int dir = blockIdx.y;
    const int rank = blockIdx.x & 1;
    const int b0 = (blockIdx.x >> 1) * 8;
    const int tid = threadIdx.x;
    const int wid = tid >> 5, lane = tid & 31;
    const int grp = lane >> 2, tq = lane & 3;

    const uint32_t mbar0 = smem_u32(&mbar[0]);
    const uint32_t mbar1 = smem_u32(&mbar[1]);
    const uint32_t pbar0 = mapa_peer(mbar0, rank ^ 1);
    const uint32_t pbar1 = mapa_peer(mbar1, rank ^ 1);
    if (tid == 0) {
        mbar_init(mbar0, 1);
        mbar_init(mbar1, 1);
    }

    // ---- preload Whh f16 A-fragments: [0..19] own k half, [20..39] peer ----
    uint32_t wreg[40];
    const bool is_mma = (wid < 15);
    const int ktL = rank * 5;           // own-half k16-tile base
    const int ktR = (rank ^ 1) * 5;
    if (is_mma) {
        const int gate = wid / 5, mseg = wid % 5;
        const int rlo = gate * Hh + rank * 80 + mseg * 16 + grp;
        const int rhi = rlo + 8;
        const float* W = dir ? whhB : whhF;
#pragma unroll
        for (int j = 0; j < 5; j++) {
            const int k0 = (ktL + j) * 16 + 2 * tq;
            wreg[j * 4 + 0] = packh2(W[(size_t)rlo * Hh + k0],     W[(size_t)rlo * Hh + k0 + 1]);
            wreg[j * 4 + 1] = packh2(W[(size_t)rhi * Hh + k0],     W[(size_t)rhi * Hh + k0 + 1]);
            wreg[j * 4 + 2] = packh2(W[(size_t)rlo * Hh + k0 + 8], W[(size_t)rlo * Hh + k0 + 9]);
            wreg[j * 4 + 3] = packh2(W[(size_t)rhi * Hh + k0 + 8], W[(size_t)rhi * Hh + k0 + 9]);
        }
#pragma unroll
        for (int j = 0; j < 5; j++) {
            const int k0 = (ktR + j) * 16 + 2 * tq;
            wreg[20 + j * 4 + 0] = packh2(W[(size_t)rlo * Hh + k0],     W[(size_t)rlo * Hh + k0 + 1]);
            wreg[20 + j * 4 + 1] = packh2(W[(size_t)rhi * Hh + k0],     W[(size_t)rhi * Hh + k0 + 1]);
            wreg[20 + j * 4 + 2] = packh2(W[(size_t)rlo * Hh + k0 + 8], W[(size_t)rlo * Hh + k0 + 9]);
            wreg[20 + j * 4 + 3] = packh2(W[(size_t)rhi * Hh + k0 + 8], W[(size_t)rhi * Hh + k0 + 9]);
        }
    }

    // ---- combine-item setup ----
    const int uA = tid >> 3, bA = tid & 7;
    const int gA = rank * 80 + uA;
    const int pgA = (gA & ~15) | hslot_rt(gA & 15);
    const float* bh = dir ? bhb : bhf;
    const float bhrA = bh[gA], bhzA = bh[Hh + gA], bhnA = bh[2 * Hh + gA];
    uint32_t prA[2];
    prA[0] = mapa_peer(smem_u32(&hbuf[0][bA * HSTH + pgA]), rank ^ 1);
    prA[1] = mapa_peer(smem_u32(&hbuf[1][bA * HSTH + pgA]), rank ^ 1);

    const bool hasB = (tid < 128);
    const int uB = 64 + (tid >> 3), gB = rank * 80 + uB;
    const int pgB = (gB & ~15) | hslot_rt(gB & 15);
    float bhrB = 0.f, bhzB = 0.f, bhnB = 0.f;
    uint32_t prB[2] = {0u, 0u};
    if (hasB) {
        bhrB = bh[gB]; bhzB = bh[Hh + gB]; bhnB = bh[2 * Hh + gB];
        prB[0] = mapa_peer(smem_u32(&hbuf[0][bA * HSTH + pgB]), rank ^ 1);
        prB[1] = mapa_peer(smem_u32(&hbuf[1][bA * HSTH + pgB]), rank ^ 1);
    }

    // ---- y0 permuted-fp16 column indices (GEMM1 fragment layout) ----
    const int cA = dir * Hh + gA;
    const int ycA = (cA & ~15) | hslot_rt(cA & 15);
    const int cB = dir * Hh + gB;
    const int ycB = (cB & ~15) | hslot_rt(cB & 15);

    // ---- gi staging: thread r<240 owns one (gate,unit) row of 8 halves ----
    const __half* gib = gi + (size_t)dir * Mrows * G3;
    const bool is_ld = (tid < GROWS);
    const int rgate = tid / 80;
    const int runit = tid - rgate * 80;
    const int rn = rgate * 160 + rank * 80 + runit;
    const __half* srcRow = gib + (size_t)rn * 256 + b0;
    const uint32_t gis_base = smem_u32(&gis[0][0]);
    const uint32_t dstRow = gis_base + (uint32_t)tid * 16;

    for (int i = tid; i < 2 * HBUFN; i += 512) (&hbuf[0][0])[i] = __float2half(0.f);

    // prologue: stage gi for s=0 into slot 0
    {
        const int t0 = dir ? (Tt - 1) : 0;
        if (is_ld) cp_async16(dstRow, srcRow + (size_t)t0 * G3 * 256);
        cp_commit();
    }

    __syncthreads();
    CLUSTER_SYNC();

    float hA = 0.f, hB = 0.f;
    int cur = 0;

    for (int s = 0; s < Tt; s++) {
        if (s + 1 < Tt) {
            const int tn = dir ? (Tt - 2 - s) : (s + 1);
            if (is_ld) cp_async16(dstRow + (cur ^ 1) * (GROWS * 16),
                                  srcRow + (size_t)tn * G3 * 256);
        }
        cp_commit();

        if (is_mma) {
            float accA[4] = {0.f, 0.f, 0.f, 0.f};
            float accB4[4] = {0.f, 0.f, 0.f, 0.f};
            const __half* hc = &hbuf[cur][grp * HSTH + tq * 4];

            // phase L: own-half k (no peer dependency), 5 mma in 2 chains
#pragma unroll
            for (int j = 0; j < 5; j++) {
                uint2 bv = *(const uint2*)(hc + (ktL + j) * 16);
                mma_f16((j & 1) ? accB4 : accA, &wreg[j * 4], bv.x, bv.y);
            }

            if (s > 0) {
                mbar_wait_parity((s & 1) ? mbar1 : mbar0, ((s - 1) >> 1) & 1);
            }

            // phase R: peer-half k, 5 mma in 2 chains
#pragma unroll
            for (int j = 0; j < 5; j++) {
                uint2 bv = *(const uint2*)(hc + (ktR + j) * 16);
                mma_f16((j & 1) ? accA : accB4, &wreg[20 + j * 4], bv.x, bv.y);
            }

            const int lr = wid * 16;
            *(float2*)&gh[(lr + grp) * 8 + 2 * tq] =
                make_float2(accA[0] + accB4[0], accA[1] + accB4[1]);
            *(float2*)&gh[(lr + 8 + grp) * 8 + 2 * tq] =
                make_float2(accA[2] + accB4[2], accA[3] + accB4[3]);
        }
        cp_wait1();
        __syncthreads();

        const int t = dir ? (Tt - 1 - s) : s;
        const int nxt = cur ^ 1;
        const __half* gs = &gis[cur][0];
        {
            float gir = __half2float(gs[(0 * 80 + uA) * 8 + bA]);
            float giz = __half2float(gs[(1 * 80 + uA) * 8 + bA]);
            float gin = __half2float(gs[(2 * 80 + uA) * 8 + bA]);
            float r = fmaf(tanh_ap(0.5f * (gir + gh[uA * 8 + bA] + bhrA)), 0.5f, 0.5f);
            float z = fmaf(tanh_ap(0.5f * (giz + gh[(80 + uA) * 8 + bA] + bhzA)), 0.5f, 0.5f);
            float n = tanh_ap(gin + r * (gh[(160 + uA) * 8 + bA] + bhnA));
            hA = fmaf(z, hA - n, n);
            __half hh = __float2half(hA);
            hbuf[nxt][bA * HSTH + pgA] = hh;
            st_cluster_u16(prA[nxt], __half_as_ushort(hh));
            if (layer == 0)
                ((__half*)yout)[((size_t)t * 256 + b0 + bA) * 320 + ycA] = hh;
        }
        if (hasB) {
            float gir = __half2float(gs[(0 * 80 + uB) * 8 + bA]);
            float giz = __half2float(gs[(1 * 80 + uB) * 8 + bA]);
            float gin = __half2float(gs[(2 * 80 + uB) * 8 + bA]);
            float r = fmaf(tanh_ap(0.5f * (gir + gh[uB * 8 + bA] + bhrB)), 0.5f, 0.5f);
            float z = fmaf(tanh_ap(0.5f * (giz + gh[(80 + uB) * 8 + bA] + bhzB)), 0.5f, 0.5f);
            float n = tanh_ap(gin + r * (gh[(160 + uB) * 8 + bA] + bhnB));
            hB = fmaf(z, hB - n, n);
            __half hh = __float2half(hB);
            hbuf[nxt][bA * HSTH + pgB] = hh;
            st_cluster_u16(prB[nxt], __half_as_ushort(hh));
            if (layer == 0)
                ((__half*)yout)[((size_t)t * 256 + b0 + bA) * 320 + ycB] = hh;
        }
        __syncthreads();   // all peer stores issued before the release below
        if (tid == 0) {
            mbar_arrive_peer((nxt & 1) ? pbar1 : pbar0);
        }
        cur = nxt;
    }

    if (layer == 1) {
        float* hf = (float*)yout;
        hf[((size_t)(dir * Bb) + b0 + bA) * Hh + gA] = hA;
        if (hasB) hf[((size_t)(dir * Bb) + b0 + bA) * Hh + gB] = hB;
    }
    CLUSTER_SYNC();   // no CTA exits while peer stores into its smem may be in flight
}

// ---------------------------------------------------------------------------
// K5: head
// ---------------------------------------------------------------------------
__global__ __launch_bounds__(128)
void head_kernel(const float* __restrict__ hfin,
                 const float* __restrict__ fc1w, const float* __restrict__ fc1b,
                 const float* __restrict__ fc2w, const float* __restrict__ fc2b,
                 float* __restrict__ out) {
    const int b = blockIdx.x;
    const int j = threadIdx.x;
    __shared__ float hv[320];
    __shared__ float red[4];

    for (int k = j; k < Hh; k += 128) {
        hv[k]      = hfin[(size_t)b * Hh + k];
        hv[Hh + k] = hfin[(size_t)Bb * Hh + (size_t)b * Hh + k];
    }
    __syncthreads();

    float acc = fc1b[j];
    const float* wr = fc1w + (size_t)j * 320;
#pragma unroll 8
    for (int k = 0; k < 320; k++) acc += wr[k] * hv[k];
    float v = fmaxf(acc, 0.f) * fc2w[j];

#pragma unroll
    for (int o = 16; o > 0; o >>= 1) v += __shfl_down_sync(0xffffffffu, v, o);
    if ((j & 31) == 0) red[j >> 5] = v;
    __syncthreads();
    if (j == 0) out[b] = red[0] + red[1] + red[2] + red[3] + fc2b[0];
}

// ---------------------------------------------------------------------------
// kernel_launch — sequential pipeline (graph-capturable, profiler-safe)
// ---------------------------------------------------------------------------
extern "C" void kernel_launch(void* const* d_in, const int* in_sizes, int n_in,
                              void* d_out, int out_size) {
    const int*   x        = (const int*)  d_in[0];
    const float* emb      = (const float*)d_in[1];
    const float* Wih_l0f  = (const float*)d_in[2];
    const float* Whh_l0f  = (const float*)d_in[3];
    const float* bih_l0f  = (const float*)d_in[4];
    const float* bhh_l0f  = (const float*)d_in[5];
    const float* Wih_l0b  = (const float*)d_in[6];
    const float* Whh_l0b  = (const float*)d_in[7];
    const float* bih_l0b  = (const float*)d_in[8];
    const float* bhh_l0b  = (const float*)d_in[9];
    const float* Wih_l1f  = (const float*)d_in[10];
    const float* Whh_l1f  = (const float*)d_in[11];
    const float* bih_l1f  = (const float*)d_in[12];
    const float* bhh_l1f  = (const float*)d_in[13];
    const float* Wih_l1b  = (const float*)d_in[14];
    const float* Whh_l1b  = (const float*)d_in[15];
    const float* bih_l1b  = (const float*)d_in[16];
    const float* bhh_l1b  = (const float*)d_in[17];
    const float* fc1_w    = (const float*)d_in[18];
    const float* fc1_b    = (const float*)d_in[19];
    const float* fc2_w    = (const float*)d_in[20];
    const float* fc2_b    = (const float*)d_in[21];
    float* out = (float*)d_out;

    __half *gi0, *gi1, *y0h, *embh, *w0h, *w1h;
    float *hfin;
    cudaGetSymbolAddress((void**)&gi0,  g_gi0);
    cudaGetSymbolAddress((void**)&gi1,  g_gi1);
    cudaGetSymbolAddress((void**)&y0h,  g_y0h);
    cudaGetSymbolAddress((void**)&embh, g_embh);
    cudaGetSymbolAddress((void**)&w0h,  g_w0h);
    cudaGetSymbolAddress((void**)&w1h,  g_w1h);
    cudaGetSymbolAddress((void**)&hfin, g_hfin);

    // K0: convert operands to permuted fp16
    {
        long long n = (long long)VV * 64;
        convert_permute_kernel<<<(unsigned)((n + 255) / 256), 256>>>(emb, embh, VV, 128);
        convert_permute_kernel<<<(G3 * 64 + 255) / 256, 256>>>(Wih_l0f, w0h, G3, 128);
        convert_permute_kernel<<<(G3 * 64 + 255) / 256, 256>>>(Wih_l0b, w0h + G3 * 128, G3, 128);
        convert_permute_kernel<<<(G3 * 160 + 255) / 256, 256>>>(Wih_l1f, w1h, G3, 320);
        convert_permute_kernel<<<(G3 * 160 + 255) / 256, 256>>>(Wih_l1b, w1h + G3 * 320, G3, 320);
    }

    {
        dim3 grid(Mrows / 128, G3 / 96, 2);
        gates_mma_kernel<128, true><<<grid, 256>>>(embh, x, w0h, bih_l0f, bih_l0b, gi0);
    }

    scan_mma_kernel<<<dim3(64, 2), 512>>>(gi0, Whh_l0f, Whh_l0b,
                                          bhh_l0f, bhh_l0b, y0h, 0);

    {
        dim3 grid(Mrows / 128, G3 / 96, 2);
        gates_mma_kernel<320, false><<<grid, 256>>>(y0h, nullptr, w1h, bih_l1f, bih_l1b, gi1);
    }

    scan_mma_kernel<<<dim3(64, 2), 512>>>(gi1, Whh_l1f, Whh_l1b,
                                          bhh_l1f, bhh_l1b, hfin, 1);

    head_kernel<<<Bb, 128>>>(hfin, fc1_w, fc1_b, fc2_w, fc2_b, out);
}